// round 1
// baseline (speedup 1.0000x reference)
#include <cuda_runtime.h>
#include <cstdint>

#define BATCH 512
#define TLEN  1024
#define NST   64

// Packed f32x2 helpers (Blackwell FFMA2 path — only reachable via PTX f32x2)
#define FMA2(d, a, b, c) asm("fma.rn.f32x2 %0, %1, %2, %3;" : "=l"(d) : "l"(a), "l"(b), "l"(c))
#define ADD2(d, a, b)    asm("add.rn.f32x2 %0, %1, %2;"     : "=l"(d) : "l"(a), "l"(b))
#define MUL2(d, a, b)    asm("mul.rn.f32x2 %0, %1, %2;"     : "=l"(d) : "l"(a), "l"(b))
#define PACK2(d, lo, hi) asm("mov.b64 %0, {%1, %2};"        : "=l"(d) : "f"(lo), "f"(hi))
#define UNPACK2(lo, hi, s) asm("mov.b64 {%0, %1}, %2;"      : "=f"(lo), "=f"(hi) : "l"(s))

__device__ __forceinline__ float fexp(float x) {
    float y;
    asm("ex2.approx.f32 %0, %1;" : "=f"(y) : "f"(x * 1.4426950408889634f));
    return y;
}
__device__ __forceinline__ float flog(float x) {
    float y;
    asm("lg2.approx.f32 %0, %1;" : "=f"(y) : "f"(x));
    return y * 0.6931471805599453f;
}

// E packed for per-thread column pairs:
// g_Epack[i*64 + 2*l + 0] = exp(trans[i][l]), g_Epack[i*64 + 2*l + 1] = exp(trans[i][l+32])
__device__ float g_Epack[NST * NST];

__global__ void prep_kernel(const float* __restrict__ trans) {
    for (int k = threadIdx.x; k < NST * 32; k += blockDim.x) {
        int i = k >> 5, l = k & 31;
        // full-precision expf here: E enters every one of 1024 steps multiplicatively
        g_Epack[i * NST + 2 * l + 0] = expf(trans[i * NST + l]);
        g_Epack[i * NST + 2 * l + 1] = expf(trans[i * NST + l + 32]);
    }
}

__global__ void __launch_bounds__(128, 1) crf_kernel(
    const float* __restrict__ unary,
    const int*   __restrict__ lengths,
    float*       __restrict__ out)
{
    const int wid = threadIdx.x >> 5;
    const int l   = threadIdx.x & 31;
    const int b   = (blockIdx.x << 2) + wid;

    // ---- E columns (l, l+32) held in registers: 64 packed f32x2 = 128 regs ----
    unsigned long long cE[NST];
    const unsigned long long* Ep = (const unsigned long long*)g_Epack;
    #pragma unroll
    for (int i = 0; i < NST; i++) cE[i] = Ep[i * 32 + l];

    // per-warp double-buffered broadcast buffer; values stored DUPLICATED
    // so the matvec can consume them directly as f32x2 without per-k packing.
    __shared__ __align__(16) float pbuf[4][2][2 * NST];

    int len = lengths[b];
    if (len < 1) len = 1;
    const float* ub = unary + (size_t)b * (TLEN * NST);

    // alpha0 = u0  ->  w = exp(u0), scale = 0
    float wx = fexp(ub[l]);
    float wy = fexp(ub[l + 32]);
    float scale = 0.0f;

    // distance-2 register prefetch of unary rows
    float ux0 = 0.f, uy0 = 0.f, ux1 = 0.f, uy1 = 0.f;
    if (len > 1) { ux0 = ub[NST + l];     uy0 = ub[NST + 32 + l]; }
    if (len > 2) { ux1 = ub[2 * NST + l]; uy1 = ub[2 * NST + 32 + l]; }
    else         { ux1 = ux0;             uy1 = uy0; }

    int buf = 0;
    for (int t = 1; t < len; t++) {
        // publish w (duplicated pairs): pbuf[.][.][2i,2i+1] = (w_i, w_i)
        float* Pw = pbuf[wid][buf];
        PACK2(*(unsigned long long*)&((float2*)Pw)[l],      wx, wx);
        PACK2(*(unsigned long long*)&((float2*)Pw)[32 + l], wy, wy);
        __syncwarp();

        // elementwise exp of current unary row (MUFU, off the FMA critical path)
        float eux = fexp(ux0);
        float euy = fexp(uy0);

        // register prefetch distance 2 + L2 prefetch distance 8
        int tn = t + 2 < len ? t + 2 : len - 1;
        const float* un = ub + (size_t)tn * NST;
        float nux = un[l];
        float nuy = un[l + 32];
        {
            int tp = t + 8 < len ? t + 8 : len - 1;
            const float* up = ub + (size_t)tp * NST + l;
            asm volatile("prefetch.global.L2 [%0];" :: "l"(up));
            asm volatile("prefetch.global.L2 [%0];" :: "l"(up + 32));
        }

        // matvec: q_(l,l+32) = sum_i w_i * E[i][(l,l+32)]  -- 64 FFMA2
        unsigned long long a0 = 0ull, a1 = 0ull, a2 = 0ull, a3 = 0ull;
        const ulonglong2* P2 = (const ulonglong2*)Pw;
        #pragma unroll
        for (int k = 0; k < NST; k += 4) {
            ulonglong2 p01 = P2[(k >> 1) + 0];
            ulonglong2 p23 = P2[(k >> 1) + 1];
            FMA2(a0, p01.x, cE[k + 0], a0);
            FMA2(a1, p01.y, cE[k + 1], a1);
            FMA2(a2, p23.x, cE[k + 2], a2);
            FMA2(a3, p23.y, cE[k + 3], a3);
        }
        unsigned long long s01, s23, q, eu2, w2;
        ADD2(s01, a0, a1);
        ADD2(s23, a2, a3);
        ADD2(q, s01, s23);
        PACK2(eu2, eux, euy);
        MUL2(w2, q, eu2);
        UNPACK2(wx, wy, w2);

        // renormalize every 4 steps (worst-case growth ~2^14.5/step)
        if ((t & 3) == 0) {
            float m = fmaxf(wx, wy);
            #pragma unroll
            for (int off = 16; off; off >>= 1)
                m = fmaxf(m, __shfl_xor_sync(0xffffffffu, m, off));
            float inv;
            asm("rcp.approx.f32 %0, %1;" : "=f"(inv) : "f"(m));
            wx *= inv;
            wy *= inv;
            scale += flog(m);
        }

        ux0 = ux1; uy0 = uy1;
        ux1 = nux; uy1 = nuy;
        buf ^= 1;
    }

    // out[b] = scale + log(sum_j w_j)
    float s = wx + wy;
    #pragma unroll
    for (int off = 16; off; off >>= 1)
        s += __shfl_xor_sync(0xffffffffu, s, off);
    if (l == 0)
        out[b] = scale + flog(s);
}

extern "C" void kernel_launch(void* const* d_in, const int* in_sizes, int n_in,
                              void* d_out, int out_size) {
    // robust input identification by element count
    const float* unary   = nullptr;
    const int*   lengths = nullptr;
    const float* trans   = nullptr;
    for (int i = 0; i < n_in; i++) {
        if (in_sizes[i] == BATCH * TLEN * NST) unary   = (const float*)d_in[i];
        else if (in_sizes[i] == BATCH)         lengths = (const int*)d_in[i];
        else if (in_sizes[i] == NST * NST)     trans   = (const float*)d_in[i];
    }
    prep_kernel<<<1, 256>>>(trans);
    crf_kernel<<<BATCH / 4, 128>>>(unary, lengths, (float*)d_out);
}